// round 14
// baseline (speedup 1.0000x reference)
#include <cuda_runtime.h>
#include <cuda_fp16.h>
#include <cstdint>

// Problem constants
#define B_    4
#define CIN   128
#define COUT  128
#define H_    32
#define W_    128
#define L_    4096
#define NH    2
#define DK    64
#define BN_EPS 1e-5f

// q is pre-scaled by 0.125 * log2(e) so softmax is exp2(S)
#define QSCALE 0.18033688011112042f

// Device scratch (fp16 operands)
__device__ __half g_qhf[B_ * L_ * COUT];   // [b][l][c]  (pre-scaled)
__device__ __half g_khf[B_ * L_ * COUT];   // [b][l][c]
__device__ __half g_vhf[B_ * COUT * L_];   // [b][c][l]
__device__ __half g_fcwh[COUT * COUT];     // fcw hi  [o][w]
__device__ __half g_fcwl[COUT * COUT];     // fcw lo  [o][w]

#define SWZ128(off) ((off) ^ (((off) >> 3) & 0x70))
#define ONE2 0x3C003C00u   // fp16 {1.0, 1.0}

__device__ __forceinline__ uint32_t smem_u32(const void* p) {
    uint32_t a;
    asm("{ .reg .u64 t; cvta.to.shared.u64 t, %1; cvt.u32.u64 %0, t; }" : "=r"(a) : "l"(p));
    return a;
}
__device__ __forceinline__ void ldsm_x4(uint32_t* r, uint32_t addr) {
    asm volatile("ldmatrix.sync.aligned.m8n8.x4.shared.b16 {%0,%1,%2,%3}, [%4];"
                 : "=r"(r[0]), "=r"(r[1]), "=r"(r[2]), "=r"(r[3]) : "r"(addr));
}
__device__ __forceinline__ void mma_f16(float* d, const uint32_t* a, const uint32_t* b) {
    asm volatile(
        "mma.sync.aligned.m16n8k16.row.col.f32.f16.f16.f32 "
        "{%0,%1,%2,%3}, {%4,%5,%6,%7}, {%8,%9}, {%0,%1,%2,%3};"
        : "+f"(d[0]), "+f"(d[1]), "+f"(d[2]), "+f"(d[3])
        : "r"(a[0]), "r"(a[1]), "r"(a[2]), "r"(a[3]), "r"(b[0]), "r"(b[1]));
}
__device__ __forceinline__ void cp16(uint32_t dst, const void* src) {
    asm volatile("cp.async.ca.shared.global [%0], [%1], 16;" :: "r"(dst), "l"(src));
}
__device__ __forceinline__ uint32_t exp2_f16x2(float lo, float hi) {
    uint32_t s, p;
    asm("cvt.rn.f16x2.f32 %0, %1, %2;" : "=r"(s) : "f"(hi), "f"(lo));
    asm("ex2.approx.f16x2 %0, %1;" : "=r"(p) : "r"(s));
    return p;
}

// ---------------------------------------------------------------------------
// Kernel 1: QKV projection via HMMA (which 0..2) + fcw hi/lo split (which==3).
// ---------------------------------------------------------------------------
#define QKV_SMEM 65536
__global__ __launch_bounds__(256, 2)
void qkv_hmma(const float* __restrict__ x,
              const float* __restrict__ wq, const float* __restrict__ bq,
              const float* __restrict__ wk, const float* __restrict__ bk,
              const float* __restrict__ wv, const float* __restrict__ bv,
              const float* __restrict__ fcw)
{
    extern __shared__ char smc[];
    const uint32_t smb = smem_u32(smc);
    const int tid = threadIdx.x, wid = tid >> 5, lane = tid & 31;
    const int lt = blockIdx.x * 128, b = blockIdx.y, which = blockIdx.z;
    const int g = lane >> 2, tig = lane & 3;

    if (which == 3) {
        // fcw hi/lo split: 16 worker blocks x 256 threads x 1 float4
        const int blk = blockIdx.y * 32 + blockIdx.x;
        if (blk < 16) {
            const int idx = blk * 256 + tid;   // 4096 float4s
            float4 v = ((const float4*)fcw)[idx];
            __half hi[4], lo[4];
            hi[0] = __float2half(v.x); lo[0] = __float2half(v.x - __half2float(hi[0]));
            hi[1] = __float2half(v.y); lo[1] = __float2half(v.y - __half2float(hi[1]));
            hi[2] = __float2half(v.z); lo[2] = __float2half(v.z - __half2float(hi[2]));
            hi[3] = __float2half(v.w); lo[3] = __float2half(v.w - __half2float(hi[3]));
            *(uint2*)&g_fcwh[idx * 4] = *(uint2*)hi;
            *(uint2*)&g_fcwl[idx * 4] = *(uint2*)lo;
        }
        return;
    }

    const float* w    = (which == 0) ? wq : (which == 1) ? wk : wv;
    const float* bias = (which == 0) ? bq : (which == 1) ? bk : bv;

    float4 xv[16];
#pragma unroll
    for (int u = 0; u < 16; u++) {
        int it = tid + u * 256;
        int l = it & 127, i4 = (it >> 7) * 4;
        const float* xp = &x[(size_t)(b * CIN + i4) * L_ + lt + l];
        xv[u].x = xp[0];
        xv[u].y = xp[L_];
        xv[u].z = xp[2 * L_];
        xv[u].w = xp[3 * L_];
    }
#pragma unroll
    for (int u = 0; u < 16; u++) {
        int it = tid + u * 256;
        int l = it & 127, i4 = (it >> 7) * 4;
        __half r[4] = {__float2half(xv[u].x), __float2half(xv[u].y),
                       __float2half(xv[u].z), __float2half(xv[u].w)};
        char* base = smc + ((i4 >> 6) ? 16384 : 0);
        *(uint2*)(base + SWZ128(l * 128 + (i4 & 63) * 2)) = *(uint2*)r;
    }
    float4 wv4[16];
#pragma unroll
    for (int u = 0; u < 16; u++) {
        int it = tid + u * 256;
        int o = it >> 5, i4 = (it & 31) * 4;
        wv4[u] = *(const float4*)&w[o * 128 + i4];
    }
#pragma unroll
    for (int u = 0; u < 16; u++) {
        int it = tid + u * 256;
        int o = it >> 5, i4 = (it & 31) * 4;
        __half r[4] = {__float2half(wv4[u].x), __float2half(wv4[u].y),
                       __float2half(wv4[u].z), __float2half(wv4[u].w)};
        char* base = smc + 32768 + ((i4 >> 6) ? 16384 : 0);
        *(uint2*)(base + SWZ128(o * 128 + (i4 & 63) * 2)) = *(uint2*)r;
    }
    __syncthreads();

    const uint32_t arow = wid * 16 + (lane & 7) + ((lane >> 3) & 1) * 8;
    const uint32_t acol = (lane >> 4) * 16;
    const uint32_t brow_lo  = (lane & 7) + ((lane >> 4) << 3);
    const uint32_t bcol_sel = ((lane >> 3) & 1) * 16;
    const int c0 = wid * 16 + g;

    float acc[16][4];
#pragma unroll
    for (int i = 0; i < 16; i++)
#pragma unroll
        for (int j = 0; j < 4; j++) acc[i][j] = 0.f;

#pragma unroll
    for (int kc = 0; kc < 8; kc++) {
        const uint32_t hoff = ((kc >> 2) ? 16384 : 0);
        const int ks = kc & 3;
        uint32_t a4[4];
        ldsm_x4(a4, smb + 32768 + hoff + SWZ128(arow * 128 + ks * 32 + acol));
#pragma unroll
        for (int np = 0; np < 8; np++) {
            uint32_t b4[4];
            ldsm_x4(b4, smb + hoff + SWZ128((np * 16 + brow_lo) * 128 + ks * 32 + bcol_sel));
            mma_f16(acc[2 * np],     a4, b4);
            mma_f16(acc[2 * np + 1], a4, b4 + 2);
        }
    }

    const float b0 = bias[c0], b1 = bias[c0 + 8];
    const float s = (which == 0) ? QSCALE : 1.0f;
    __syncthreads();

    if (which < 2) {
        __half* st = (__half*)smc;
#pragma unroll
        for (int nt = 0; nt < 16; nt++) {
            const int l0 = nt * 8 + tig * 2;
            st[l0 * 128 + c0]           = __float2half((acc[nt][0] + b0) * s);
            st[(l0 + 1) * 128 + c0]     = __float2half((acc[nt][1] + b0) * s);
            st[l0 * 128 + c0 + 8]       = __float2half((acc[nt][2] + b1) * s);
            st[(l0 + 1) * 128 + c0 + 8] = __float2half((acc[nt][3] + b1) * s);
        }
        __syncthreads();
        __half* dst = (which == 0) ? g_qhf : g_khf;
        uint4* dg = (uint4*)&dst[(size_t)(b * L_ + lt) * 128];
        const uint4* sg = (const uint4*)smc;
        for (int i = tid; i < 2048; i += 256) dg[i] = sg[i];
    } else {
        uint32_t* st = (uint32_t*)smc;
#pragma unroll
        for (int nt = 0; nt < 16; nt++) {
            const int lp = (nt * 8 + tig * 2) >> 1;
            __half2 v0 = __floats2half2_rn(acc[nt][0] + b0, acc[nt][1] + b0);
            __half2 v1 = __floats2half2_rn(acc[nt][2] + b1, acc[nt][3] + b1);
            st[c0 * 64 + lp]       = *(uint32_t*)&v0;
            st[(c0 + 8) * 64 + lp] = *(uint32_t*)&v1;
        }
        __syncthreads();
        for (int i = tid; i < 2048; i += 256) {
            int c = i >> 4, seg = i & 15;
            *(uint4*)&g_vhf[(size_t)(b * COUT + c) * L_ + lt + seg * 8] =
                ((const uint4*)smc)[i];
        }
    }
}

// ---------------------------------------------------------------------------
// Kernel 2: FMHA + FUSED fc/BN/PReLU (structure unchanged from R13).
// ---------------------------------------------------------------------------
#define OFF_Q   0
#define OFF_S   16384
#define SMEM_ATTN 114688

__device__ __forceinline__ void load_kv_tile(uint32_t smb, int tid, int b, int head,
                                             int kt, int s)
{
    const char* kb = (const char*)g_khf;
    const uint32_t kdst = smb + OFF_S + s * 32768;
    for (int i = tid; i < 1024; i += 128) {
        int r = i >> 3, ch = i & 7;
        const char* src = kb + ((size_t)(b * L_ + kt + r) * COUT + head * DK) * 2 + ch * 16;
        cp16(kdst + SWZ128(r * 128 + ch * 16), src);
    }
    const char* vb = (const char*)g_vhf;
    const uint32_t vdst = kdst + 16384;
    for (int i = tid; i < 1024; i += 128) {
        int half = i >> 9, rem = i & 511;
        int d = rem >> 3, ch = rem & 7;
        const char* src = vb + ((size_t)(b * COUT + head * DK + d) * L_ + kt + half * 64 + ch * 8) * 2;
        cp16(vdst + half * 8192 + SWZ128(d * 128 + ch * 16), src);
    }
}

__global__ __launch_bounds__(128, 2)
void attn_fused_kernel(const float* __restrict__ fcb,
                       const float* __restrict__ gamma, const float* __restrict__ beta,
                       const float* __restrict__ mean,  const float* __restrict__ var,
                       const float* __restrict__ prelu, float* __restrict__ y)
{
    extern __shared__ char smc[];
    const uint32_t smb = smem_u32(smc);

    const int tid  = threadIdx.x;
    const int wid  = tid >> 5;
    const int lane = tid & 31;
    const int hidx = blockIdx.x;        // h row (qt = hidx*128)
    const int qt   = hidx * 128;
    const int head = blockIdx.y;
    const int b    = blockIdx.z;

    const int g   = lane >> 2;
    const int tig = lane & 3;

    // ---- prologue: Q + tiles 0 and 1 ----
    {
        const char* qb = (const char*)g_qhf;
        for (int i = tid; i < 1024; i += 128) {
            int r = i >> 3, ch = i & 7;
            const char* src = qb + ((size_t)(b * L_ + qt + r) * COUT + head * DK) * 2 + ch * 16;
            cp16(smb + OFF_Q + SWZ128(r * 128 + ch * 16), src);
        }
        load_kv_tile(smb, tid, b, head, 0, 0);
        asm volatile("cp.async.commit_group;" ::: "memory");
        load_kv_tile(smb, tid, b, head, 128, 1);
        asm volatile("cp.async.commit_group;" ::: "memory");
    }

    uint32_t qhr[2][4][4];
    float O[2][8][4];
    float Osum[2][4];
#pragma unroll
    for (int mi = 0; mi < 2; mi++) {
#pragma unroll
        for (int i = 0; i < 8; i++)
#pragma unroll
            for (int j = 0; j < 4; j++) O[mi][i][j] = 0.f;
#pragma unroll
        for (int j = 0; j < 4; j++) Osum[mi][j] = 0.f;
    }
    const uint32_t ones[2] = {ONE2, ONE2};

    const uint32_t brow_lo  = (lane & 7) + ((lane >> 4) << 3);
    const uint32_t bcol_sel = ((lane >> 3) & 1) * 16;

    int buf = 0;
    for (int t = 0; t < 32; t++) {
        if (t < 31) {
            asm volatile("cp.async.wait_group 1;" ::: "memory");
        } else {
            asm volatile("cp.async.wait_group 0;" ::: "memory");
        }
        __syncthreads();

        if (t == 0) {
#pragma unroll
            for (int mi = 0; mi < 2; mi++) {
                const uint32_t arow = wid * 32 + mi * 16 + (lane & 7) + ((lane >> 3) & 1) * 8;
#pragma unroll
                for (int ks = 0; ks < 4; ks++) {
                    uint32_t colb = ks * 32 + (lane >> 4) * 16;
                    ldsm_x4(qhr[mi][ks], smb + OFF_Q + SWZ128(arow * 128 + colb));
                }
            }
        }

        const uint32_t kbase = smb + OFF_S + buf * 32768;
        const uint32_t vbase = kbase + 16384;

#pragma unroll
        for (int nb = 0; nb < 8; nb++) {
            float S8[2][2][4];
#pragma unroll
            for (int mi = 0; mi < 2; mi++)
#pragma unroll
                for (int i = 0; i < 2; i++)
#pragma unroll
                    for (int j = 0; j < 4; j++) S8[mi][i][j] = 0.f;

            const uint32_t krow = nb * 16 + brow_lo;
#pragma unroll
            for (int ks = 0; ks < 4; ks++) {
                uint32_t bh[4];
                ldsm_x4(bh, kbase + SWZ128(krow * 128 + ks * 32 + bcol_sel));
                mma_f16(S8[0][0], qhr[0][ks], bh);
                mma_f16(S8[0][1], qhr[0][ks], bh + 2);
                mma_f16(S8[1][0], qhr[1][ks], bh);
                mma_f16(S8[1][1], qhr[1][ks], bh + 2);
            }

            uint32_t pf[2][4];
#pragma unroll
            for (int mi = 0; mi < 2; mi++) {
                pf[mi][0] = exp2_f16x2(S8[mi][0][0], S8[mi][0][1]);
                pf[mi][1] = exp2_f16x2(S8[mi][0][2], S8[mi][0][3]);
                pf[mi][2] = exp2_f16x2(S8[mi][1][0], S8[mi][1][1]);
                pf[mi][3] = exp2_f16x2(S8[mi][1][2], S8[mi][1][3]);
                mma_f16(Osum[mi], pf[mi], ones);
            }

            const uint32_t vb2 = vbase + ((nb >= 4) ? 8192 : 0);
#pragma unroll
            for (int dp = 0; dp < 4; dp++) {
                uint32_t vfr[4];
                uint32_t row = dp * 16 + brow_lo;
                ldsm_x4(vfr, vb2 + SWZ128(row * 128 + (nb & 3) * 32 + bcol_sel));
                mma_f16(O[0][2 * dp],     pf[0], vfr);
                mma_f16(O[0][2 * dp + 1], pf[0], vfr + 2);
                mma_f16(O[1][2 * dp],     pf[1], vfr);
                mma_f16(O[1][2 * dp + 1], pf[1], vfr + 2);
            }
        }

        if (t + 2 < 32) {
            int nbuf = buf + 2; if (nbuf >= 3) nbuf -= 3;
            load_kv_tile(smb, tid, b, head, (t + 2) * 128, nbuf);
            asm volatile("cp.async.commit_group;" ::: "memory");
        }
        buf = (buf + 1 == 3) ? 0 : buf + 1;
    }

    // ================= FUSED fc EPILOGUE =================
    __syncthreads();   // all warps done with ring smem

    // ---- issue fcw hi/lo prefetch (F tiles @32768 hi, @65536 lo; 2x16K halves)
    {
        const char* fh = (const char*)g_fcwh;
        const char* fl = (const char*)g_fcwl;
        for (int i = tid; i < 2048; i += 128) {
            int o = i >> 4, seg = i & 15;
            int half = seg >> 3, c8 = seg & 7;
            uint32_t dst = half * 16384 + SWZ128(o * 128 + c8 * 16);
            size_t src = (size_t)o * 256 + half * 128 + c8 * 16;
            cp16(smb + 32768 + dst, fh + src);
            cp16(smb + 65536 + dst, fl + src);
        }
        asm volatile("cp.async.commit_group;" ::: "memory");
    }

    // ---- stage normalized O as hi/lo [c][w] tiles (A @0 hi, @16384 lo; halves +8192)
#pragma unroll
    for (int mi = 0; mi < 2; mi++) {
        const float inv0 = 1.f / Osum[mi][0];
        const float inv1 = 1.f / Osum[mi][2];
        const int q0 = wid * 32 + mi * 16 + g;
#pragma unroll
        for (int dt = 0; dt < 8; dt++) {
            const int c = dt * 8 + 2 * tig;
            float vals[4] = {O[mi][dt][0] * inv0, O[mi][dt][1] * inv0,
                             O[mi][dt][2] * inv1, O[mi][dt][3] * inv1};
            const int ws[4] = {q0, q0, q0 + 8, q0 + 8};
            const int cs[4] = {c, c + 1, c, c + 1};
#pragma unroll
            for (int j = 0; j < 4; j++) {
                __half hi = __float2half(vals[j]);
                __half lo = __float2half(vals[j] - __half2float(hi));
                const int w = ws[j];
                uint32_t off = ((w >> 6) ? 8192 : 0) + SWZ128(cs[j] * 128 + (w & 63) * 2);
                *(__half*)(smc + off)         = hi;
                *(__half*)(smc + 16384 + off) = lo;
            }
        }
    }
    asm volatile("cp.async.wait_group 0;" ::: "memory");
    __syncthreads();

    // ---- per-warp GEMM: 16 c-rows x 128 o, K = 128 w, hi/lo 3-product ----
    const uint32_t arow = wid * 16 + (lane & 7) + ((lane >> 3) & 1) * 8;
    const uint32_t acol = (lane >> 4) * 16;

    float acc[16][4];
#pragma unroll
    for (int i = 0; i < 16; i++)
#pragma unroll
        for (int j = 0; j < 4; j++) acc[i][j] = 0.f;

#pragma unroll
    for (int kc = 0; kc < 8; kc++) {
        const int ks = kc & 3;
        const uint32_t ahalf = (kc >> 2) ? 8192 : 0;
        const uint32_t fhalf = (kc >> 2) ? 16384 : 0;
        uint32_t ah[4], al[4];
        const uint32_t aoff = ahalf + SWZ128(arow * 128 + ks * 32 + acol);
        ldsm_x4(ah, smb + aoff);
        ldsm_x4(al, smb + 16384 + aoff);

        uint32_t bh[8][4], bl[8][4];
#pragma unroll
        for (int np = 0; np < 8; np++) {
            const uint32_t boff = fhalf + SWZ128((np * 16 + brow_lo) * 128 + ks * 32 + bcol_sel);
            ldsm_x4(bh[np], smb + 32768 + boff);
            ldsm_x4(bl[np], smb + 65536 + boff);
        }
#pragma unroll
        for (int np = 0; np < 8; np++) {
            mma_f16(acc[2 * np],     ah, bh[np]);
            mma_f16(acc[2 * np + 1], ah, bh[np] + 2);
        }
#pragma unroll
        for (int np = 0; np < 8; np++) {
            mma_f16(acc[2 * np],     ah, bl[np]);
            mma_f16(acc[2 * np + 1], ah, bl[np] + 2);
        }
#pragma unroll
        for (int np = 0; np < 8; np++) {
            mma_f16(acc[2 * np],     al, bh[np]);
            mma_f16(acc[2 * np + 1], al, bh[np] + 2);
        }
    }

    // ---- bias + BN + PReLU -> y[b][c][h][o] ----
    const float slope = prelu[0];
#pragma unroll
    for (int half = 0; half < 2; half++) {
        const int cr = wid * 16 + g + 8 * half;     // c row within head (0..63)
        const int c_glob = head * DK + cr;          // BN channel
        const size_t r = ((size_t)(b * COUT + c_glob) * H_ + hidx);
        const float sc = rsqrtf(var[c_glob] + BN_EPS) * gamma[c_glob];
        const float sh = beta[c_glob] - mean[c_glob] * sc;
#pragma unroll
        for (int nt = 0; nt < 16; nt++) {
            const int o = nt * 8 + tig * 2;
            float v0 = (acc[nt][2 * half]     + fcb[o])     * sc + sh;
            float v1 = (acc[nt][2 * half + 1] + fcb[o + 1]) * sc + sh;
            v0 = (v0 > 0.f) ? v0 : slope * v0;
            v1 = (v1 > 0.f) ? v1 : slope * v1;
            *(float2*)&y[r * W_ + o] = make_float2(v0, v1);
        }
    }
}

// ---------------------------------------------------------------------------
extern "C" void kernel_launch(void* const* d_in, const int* in_sizes, int n_in,
                              void* d_out, int out_size)
{
    const float* x     = (const float*)d_in[0];
    const float* wq    = (const float*)d_in[1];
    const float* bq    = (const float*)d_in[2];
    const float* wk    = (const float*)d_in[3];
    const float* bk    = (const float*)d_in[4];
    const float* wv    = (const float*)d_in[5];
    const float* bv    = (const float*)d_in[6];
    const float* fc_w  = (const float*)d_in[7];
    const float* fc_b  = (const float*)d_in[8];
    const float* gam   = (const float*)d_in[9];
    const float* bet   = (const float*)d_in[10];
    const float* mean  = (const float*)d_in[11];
    const float* var   = (const float*)d_in[12];
    const float* prelu = (const float*)d_in[13];
    float* y = (float*)d_out;

    cudaFuncSetAttribute(qkv_hmma, cudaFuncAttributeMaxDynamicSharedMemorySize, QKV_SMEM);
    cudaFuncSetAttribute(attn_fused_kernel, cudaFuncAttributeMaxDynamicSharedMemorySize, SMEM_ATTN);

    qkv_hmma<<<dim3(32, B_, 4), 256, QKV_SMEM>>>(x, wq, bq, wk, bk, wv, bv, fc_w);
    attn_fused_kernel<<<dim3(L_ / 128, NH, B_), 128, SMEM_ATTN>>>(
        fc_b, gam, bet, mean, var, prelu, y);
}

// round 15
// speedup vs baseline: 1.0134x; 1.0134x over previous
#include <cuda_runtime.h>
#include <cuda_fp16.h>
#include <cstdint>

// Problem constants
#define B_    4
#define CIN   128
#define COUT  128
#define H_    32
#define W_    128
#define L_    4096
#define NH    2
#define DK    64
#define BN_EPS 1e-5f

// q is pre-scaled by 0.125 * log2(e) so softmax is exp2(S)
#define QSCALE 0.18033688011112042f

// Device scratch (fp16 operands)
__device__ __half g_qhf[B_ * L_ * COUT];   // [b][l][c]  (pre-scaled)
__device__ __half g_khf[B_ * L_ * COUT];   // [b][l][c]
__device__ __half g_vhf[B_ * COUT * L_];   // [b][c][l]
__device__ __half g_fcwh[COUT * COUT];     // fcw hi  [o][w]
__device__ __half g_fcwl[COUT * COUT];     // fcw lo  [o][w]

#define SWZ128(off) ((off) ^ (((off) >> 3) & 0x70))
#define ONE2 0x3C003C00u   // fp16 {1.0, 1.0}

__device__ __forceinline__ uint32_t smem_u32(const void* p) {
    uint32_t a;
    asm("{ .reg .u64 t; cvta.to.shared.u64 t, %1; cvt.u32.u64 %0, t; }" : "=r"(a) : "l"(p));
    return a;
}
__device__ __forceinline__ void ldsm_x4(uint32_t* r, uint32_t addr) {
    asm volatile("ldmatrix.sync.aligned.m8n8.x4.shared.b16 {%0,%1,%2,%3}, [%4];"
                 : "=r"(r[0]), "=r"(r[1]), "=r"(r[2]), "=r"(r[3]) : "r"(addr));
}
__device__ __forceinline__ void mma_f16(float* d, const uint32_t* a, const uint32_t* b) {
    asm volatile(
        "mma.sync.aligned.m16n8k16.row.col.f32.f16.f16.f32 "
        "{%0,%1,%2,%3}, {%4,%5,%6,%7}, {%8,%9}, {%0,%1,%2,%3};"
        : "+f"(d[0]), "+f"(d[1]), "+f"(d[2]), "+f"(d[3])
        : "r"(a[0]), "r"(a[1]), "r"(a[2]), "r"(a[3]), "r"(b[0]), "r"(b[1]));
}
__device__ __forceinline__ void cp16(uint32_t dst, const void* src) {
    asm volatile("cp.async.ca.shared.global [%0], [%1], 16;" :: "r"(dst), "l"(src));
}
__device__ __forceinline__ uint32_t exp2_f16x2(float lo, float hi) {
    uint32_t s, p;
    asm("cvt.rn.f16x2.f32 %0, %1, %2;" : "=r"(s) : "f"(hi), "f"(lo));
    asm("ex2.approx.f16x2 %0, %1;" : "=r"(p) : "r"(s));
    return p;
}

// ---------------------------------------------------------------------------
// Kernel 1: QKV projection via HMMA (which 0..2) + fcw hi/lo split (which==3).
// ---------------------------------------------------------------------------
#define QKV_SMEM 65536
__global__ __launch_bounds__(256, 2)
void qkv_hmma(const float* __restrict__ x,
              const float* __restrict__ wq, const float* __restrict__ bq,
              const float* __restrict__ wk, const float* __restrict__ bk,
              const float* __restrict__ wv, const float* __restrict__ bv,
              const float* __restrict__ fcw)
{
    extern __shared__ char smc[];
    const uint32_t smb = smem_u32(smc);
    const int tid = threadIdx.x, wid = tid >> 5, lane = tid & 31;
    const int lt = blockIdx.x * 128, b = blockIdx.y, which = blockIdx.z;
    const int g = lane >> 2, tig = lane & 3;

    if (which == 3) {
        const int blk = blockIdx.y * 32 + blockIdx.x;
        if (blk < 16) {
            const int idx = blk * 256 + tid;   // 4096 float4s
            float4 v = ((const float4*)fcw)[idx];
            __half hi[4], lo[4];
            hi[0] = __float2half(v.x); lo[0] = __float2half(v.x - __half2float(hi[0]));
            hi[1] = __float2half(v.y); lo[1] = __float2half(v.y - __half2float(hi[1]));
            hi[2] = __float2half(v.z); lo[2] = __float2half(v.z - __half2float(hi[2]));
            hi[3] = __float2half(v.w); lo[3] = __float2half(v.w - __half2float(hi[3]));
            *(uint2*)&g_fcwh[idx * 4] = *(uint2*)hi;
            *(uint2*)&g_fcwl[idx * 4] = *(uint2*)lo;
        }
        return;
    }

    const float* w    = (which == 0) ? wq : (which == 1) ? wk : wv;
    const float* bias = (which == 0) ? bq : (which == 1) ? bk : bv;

    float4 xv[16];
#pragma unroll
    for (int u = 0; u < 16; u++) {
        int it = tid + u * 256;
        int l = it & 127, i4 = (it >> 7) * 4;
        const float* xp = &x[(size_t)(b * CIN + i4) * L_ + lt + l];
        xv[u].x = xp[0];
        xv[u].y = xp[L_];
        xv[u].z = xp[2 * L_];
        xv[u].w = xp[3 * L_];
    }
#pragma unroll
    for (int u = 0; u < 16; u++) {
        int it = tid + u * 256;
        int l = it & 127, i4 = (it >> 7) * 4;
        __half r[4] = {__float2half(xv[u].x), __float2half(xv[u].y),
                       __float2half(xv[u].z), __float2half(xv[u].w)};
        char* base = smc + ((i4 >> 6) ? 16384 : 0);
        *(uint2*)(base + SWZ128(l * 128 + (i4 & 63) * 2)) = *(uint2*)r;
    }
    float4 wv4[16];
#pragma unroll
    for (int u = 0; u < 16; u++) {
        int it = tid + u * 256;
        int o = it >> 5, i4 = (it & 31) * 4;
        wv4[u] = *(const float4*)&w[o * 128 + i4];
    }
#pragma unroll
    for (int u = 0; u < 16; u++) {
        int it = tid + u * 256;
        int o = it >> 5, i4 = (it & 31) * 4;
        __half r[4] = {__float2half(wv4[u].x), __float2half(wv4[u].y),
                       __float2half(wv4[u].z), __float2half(wv4[u].w)};
        char* base = smc + 32768 + ((i4 >> 6) ? 16384 : 0);
        *(uint2*)(base + SWZ128(o * 128 + (i4 & 63) * 2)) = *(uint2*)r;
    }
    __syncthreads();

    const uint32_t arow = wid * 16 + (lane & 7) + ((lane >> 3) & 1) * 8;
    const uint32_t acol = (lane >> 4) * 16;
    const uint32_t brow_lo  = (lane & 7) + ((lane >> 4) << 3);
    const uint32_t bcol_sel = ((lane >> 3) & 1) * 16;
    const int c0 = wid * 16 + g;

    float acc[16][4];
#pragma unroll
    for (int i = 0; i < 16; i++)
#pragma unroll
        for (int j = 0; j < 4; j++) acc[i][j] = 0.f;

#pragma unroll
    for (int kc = 0; kc < 8; kc++) {
        const uint32_t hoff = ((kc >> 2) ? 16384 : 0);
        const int ks = kc & 3;
        uint32_t a4[4];
        ldsm_x4(a4, smb + 32768 + hoff + SWZ128(arow * 128 + ks * 32 + acol));
#pragma unroll
        for (int np = 0; np < 8; np++) {
            uint32_t b4[4];
            ldsm_x4(b4, smb + hoff + SWZ128((np * 16 + brow_lo) * 128 + ks * 32 + bcol_sel));
            mma_f16(acc[2 * np],     a4, b4);
            mma_f16(acc[2 * np + 1], a4, b4 + 2);
        }
    }

    const float b0 = bias[c0], b1 = bias[c0 + 8];
    const float s = (which == 0) ? QSCALE : 1.0f;
    __syncthreads();

    if (which < 2) {
        __half* st = (__half*)smc;
#pragma unroll
        for (int nt = 0; nt < 16; nt++) {
            const int l0 = nt * 8 + tig * 2;
            st[l0 * 128 + c0]           = __float2half((acc[nt][0] + b0) * s);
            st[(l0 + 1) * 128 + c0]     = __float2half((acc[nt][1] + b0) * s);
            st[l0 * 128 + c0 + 8]       = __float2half((acc[nt][2] + b1) * s);
            st[(l0 + 1) * 128 + c0 + 8] = __float2half((acc[nt][3] + b1) * s);
        }
        __syncthreads();
        __half* dst = (which == 0) ? g_qhf : g_khf;
        uint4* dg = (uint4*)&dst[(size_t)(b * L_ + lt) * 128];
        const uint4* sg = (const uint4*)smc;
        for (int i = tid; i < 2048; i += 256) dg[i] = sg[i];
    } else {
        uint32_t* st = (uint32_t*)smc;
#pragma unroll
        for (int nt = 0; nt < 16; nt++) {
            const int lp = (nt * 8 + tig * 2) >> 1;
            __half2 v0 = __floats2half2_rn(acc[nt][0] + b0, acc[nt][1] + b0);
            __half2 v1 = __floats2half2_rn(acc[nt][2] + b1, acc[nt][3] + b1);
            st[c0 * 64 + lp]       = *(uint32_t*)&v0;
            st[(c0 + 8) * 64 + lp] = *(uint32_t*)&v1;
        }
        __syncthreads();
        for (int i = tid; i < 2048; i += 256) {
            int c = i >> 4, seg = i & 15;
            *(uint4*)&g_vhf[(size_t)(b * COUT + c) * L_ + lt + seg * 8] =
                ((const uint4*)smc)[i];
        }
    }
}

// ---------------------------------------------------------------------------
// Kernel 2: FMHA + FUSED fc/BN/PReLU. Epilogue GEMM restructured to
// per-np streaming fragment loads (low register pressure, no spills).
// ---------------------------------------------------------------------------
#define OFF_Q   0
#define OFF_S   16384
#define SMEM_ATTN 114688

__device__ __forceinline__ void load_kv_tile(uint32_t smb, int tid, int b, int head,
                                             int kt, int s)
{
    const char* kb = (const char*)g_khf;
    const uint32_t kdst = smb + OFF_S + s * 32768;
    for (int i = tid; i < 1024; i += 128) {
        int r = i >> 3, ch = i & 7;
        const char* src = kb + ((size_t)(b * L_ + kt + r) * COUT + head * DK) * 2 + ch * 16;
        cp16(kdst + SWZ128(r * 128 + ch * 16), src);
    }
    const char* vb = (const char*)g_vhf;
    const uint32_t vdst = kdst + 16384;
    for (int i = tid; i < 1024; i += 128) {
        int half = i >> 9, rem = i & 511;
        int d = rem >> 3, ch = rem & 7;
        const char* src = vb + ((size_t)(b * COUT + head * DK + d) * L_ + kt + half * 64 + ch * 8) * 2;
        cp16(vdst + half * 8192 + SWZ128(d * 128 + ch * 16), src);
    }
}

__global__ __launch_bounds__(128, 2)
void attn_fused_kernel(const float* __restrict__ fcb,
                       const float* __restrict__ gamma, const float* __restrict__ beta,
                       const float* __restrict__ mean,  const float* __restrict__ var,
                       const float* __restrict__ prelu, float* __restrict__ y)
{
    extern __shared__ char smc[];
    const uint32_t smb = smem_u32(smc);

    const int tid  = threadIdx.x;
    const int wid  = tid >> 5;
    const int lane = tid & 31;
    const int hidx = blockIdx.x;        // h row (qt = hidx*128)
    const int qt   = hidx * 128;
    const int head = blockIdx.y;
    const int b    = blockIdx.z;

    const int g   = lane >> 2;
    const int tig = lane & 3;

    // ---- prologue: Q + tiles 0 and 1 ----
    {
        const char* qb = (const char*)g_qhf;
        for (int i = tid; i < 1024; i += 128) {
            int r = i >> 3, ch = i & 7;
            const char* src = qb + ((size_t)(b * L_ + qt + r) * COUT + head * DK) * 2 + ch * 16;
            cp16(smb + OFF_Q + SWZ128(r * 128 + ch * 16), src);
        }
        load_kv_tile(smb, tid, b, head, 0, 0);
        asm volatile("cp.async.commit_group;" ::: "memory");
        load_kv_tile(smb, tid, b, head, 128, 1);
        asm volatile("cp.async.commit_group;" ::: "memory");
    }

    uint32_t qhr[2][4][4];
    float O[2][8][4];
    float Osum[2][4];
#pragma unroll
    for (int mi = 0; mi < 2; mi++) {
#pragma unroll
        for (int i = 0; i < 8; i++)
#pragma unroll
            for (int j = 0; j < 4; j++) O[mi][i][j] = 0.f;
#pragma unroll
        for (int j = 0; j < 4; j++) Osum[mi][j] = 0.f;
    }
    const uint32_t ones[2] = {ONE2, ONE2};

    const uint32_t brow_lo  = (lane & 7) + ((lane >> 4) << 3);
    const uint32_t bcol_sel = ((lane >> 3) & 1) * 16;

    int buf = 0;
    for (int t = 0; t < 32; t++) {
        if (t < 31) {
            asm volatile("cp.async.wait_group 1;" ::: "memory");
        } else {
            asm volatile("cp.async.wait_group 0;" ::: "memory");
        }
        __syncthreads();

        if (t == 0) {
#pragma unroll
            for (int mi = 0; mi < 2; mi++) {
                const uint32_t arow = wid * 32 + mi * 16 + (lane & 7) + ((lane >> 3) & 1) * 8;
#pragma unroll
                for (int ks = 0; ks < 4; ks++) {
                    uint32_t colb = ks * 32 + (lane >> 4) * 16;
                    ldsm_x4(qhr[mi][ks], smb + OFF_Q + SWZ128(arow * 128 + colb));
                }
            }
        }

        const uint32_t kbase = smb + OFF_S + buf * 32768;
        const uint32_t vbase = kbase + 16384;

#pragma unroll
        for (int nb = 0; nb < 8; nb++) {
            float S8[2][2][4];
#pragma unroll
            for (int mi = 0; mi < 2; mi++)
#pragma unroll
                for (int i = 0; i < 2; i++)
#pragma unroll
                    for (int j = 0; j < 4; j++) S8[mi][i][j] = 0.f;

            const uint32_t krow = nb * 16 + brow_lo;
#pragma unroll
            for (int ks = 0; ks < 4; ks++) {
                uint32_t bh[4];
                ldsm_x4(bh, kbase + SWZ128(krow * 128 + ks * 32 + bcol_sel));
                mma_f16(S8[0][0], qhr[0][ks], bh);
                mma_f16(S8[0][1], qhr[0][ks], bh + 2);
                mma_f16(S8[1][0], qhr[1][ks], bh);
                mma_f16(S8[1][1], qhr[1][ks], bh + 2);
            }

            uint32_t pf[2][4];
#pragma unroll
            for (int mi = 0; mi < 2; mi++) {
                pf[mi][0] = exp2_f16x2(S8[mi][0][0], S8[mi][0][1]);
                pf[mi][1] = exp2_f16x2(S8[mi][0][2], S8[mi][0][3]);
                pf[mi][2] = exp2_f16x2(S8[mi][1][0], S8[mi][1][1]);
                pf[mi][3] = exp2_f16x2(S8[mi][1][2], S8[mi][1][3]);
                mma_f16(Osum[mi], pf[mi], ones);
            }

            const uint32_t vb2 = vbase + ((nb >= 4) ? 8192 : 0);
#pragma unroll
            for (int dp = 0; dp < 4; dp++) {
                uint32_t vfr[4];
                uint32_t row = dp * 16 + brow_lo;
                ldsm_x4(vfr, vb2 + SWZ128(row * 128 + (nb & 3) * 32 + bcol_sel));
                mma_f16(O[0][2 * dp],     pf[0], vfr);
                mma_f16(O[0][2 * dp + 1], pf[0], vfr + 2);
                mma_f16(O[1][2 * dp],     pf[1], vfr);
                mma_f16(O[1][2 * dp + 1], pf[1], vfr + 2);
            }
        }

        if (t + 2 < 32) {
            int nbuf = buf + 2; if (nbuf >= 3) nbuf -= 3;
            load_kv_tile(smb, tid, b, head, (t + 2) * 128, nbuf);
            asm volatile("cp.async.commit_group;" ::: "memory");
        }
        buf = (buf + 1 == 3) ? 0 : buf + 1;
    }

    // ================= FUSED fc EPILOGUE (low-register form) =================
    __syncthreads();   // all warps done with ring smem

    // ---- issue fcw hi/lo prefetch (F tiles @32768 hi, @65536 lo; 2x16K halves)
    {
        const char* fh = (const char*)g_fcwh;
        const char* fl = (const char*)g_fcwl;
        for (int i = tid; i < 2048; i += 128) {
            int o = i >> 4, seg = i & 15;
            int half = seg >> 3, c8 = seg & 7;
            uint32_t dst = half * 16384 + SWZ128(o * 128 + c8 * 16);
            size_t src = (size_t)o * 256 + half * 128 + c8 * 16;
            cp16(smb + 32768 + dst, fh + src);
            cp16(smb + 65536 + dst, fl + src);
        }
        asm volatile("cp.async.commit_group;" ::: "memory");
    }

    // ---- stage normalized O as hi/lo [c][w] tiles (A @0 hi, @16384 lo; halves +8192)
#pragma unroll
    for (int mi = 0; mi < 2; mi++) {
        const float inv0 = 1.f / Osum[mi][0];
        const float inv1 = 1.f / Osum[mi][2];
        const int q0 = wid * 32 + mi * 16 + g;
#pragma unroll
        for (int dt = 0; dt < 8; dt++) {
            const int c = dt * 8 + 2 * tig;
            float vals[4] = {O[mi][dt][0] * inv0, O[mi][dt][1] * inv0,
                             O[mi][dt][2] * inv1, O[mi][dt][3] * inv1};
            const int ws[4] = {q0, q0, q0 + 8, q0 + 8};
            const int cs[4] = {c, c + 1, c, c + 1};
#pragma unroll
            for (int j = 0; j < 4; j++) {
                __half hi = __float2half(vals[j]);
                __half lo = __float2half(vals[j] - __half2float(hi));
                const int w = ws[j];
                uint32_t off = ((w >> 6) ? 8192 : 0) + SWZ128(cs[j] * 128 + (w & 63) * 2);
                *(__half*)(smc + off)         = hi;
                *(__half*)(smc + 16384 + off) = lo;
            }
        }
    }
    asm volatile("cp.async.wait_group 0;" ::: "memory");
    __syncthreads();

    // ---- per-warp GEMM: 16 c-rows x 128 o, K = 128 w; per-np streaming frags
    const uint32_t arow = wid * 16 + (lane & 7) + ((lane >> 3) & 1) * 8;
    const uint32_t acol = (lane >> 4) * 16;

    float acc[16][4];
#pragma unroll
    for (int i = 0; i < 16; i++)
#pragma unroll
        for (int j = 0; j < 4; j++) acc[i][j] = 0.f;

#pragma unroll
    for (int kc = 0; kc < 8; kc++) {
        const int ks = kc & 3;
        const uint32_t ahalf = (kc >> 2) ? 8192 : 0;
        const uint32_t fhalf = (kc >> 2) ? 16384 : 0;
        uint32_t ah[4], al[4];
        const uint32_t aoff = ahalf + SWZ128(arow * 128 + ks * 32 + acol);
        ldsm_x4(ah, smb + aoff);
        ldsm_x4(al, smb + 16384 + aoff);

#pragma unroll
        for (int np = 0; np < 8; np++) {
            const uint32_t boff = fhalf + SWZ128((np * 16 + brow_lo) * 128 + ks * 32 + bcol_sel);
            uint32_t bh[4], bl[4];
            ldsm_x4(bh, smb + 32768 + boff);
            mma_f16(acc[2 * np],     ah, bh);
            mma_f16(acc[2 * np + 1], ah, bh + 2);
            ldsm_x4(bl, smb + 65536 + boff);
            mma_f16(acc[2 * np],     al, bh);
            mma_f16(acc[2 * np + 1], al, bh + 2);
            mma_f16(acc[2 * np],     ah, bl);
            mma_f16(acc[2 * np + 1], ah, bl + 2);
        }
    }

    // ---- bias + BN + PReLU -> y[b][c][h][o] ----
    const float slope = prelu[0];
#pragma unroll
    for (int half = 0; half < 2; half++) {
        const int cr = wid * 16 + g + 8 * half;     // c row within head (0..63)
        const int c_glob = head * DK + cr;          // BN channel
        const size_t r = ((size_t)(b * COUT + c_glob) * H_ + hidx);
        const float sc = rsqrtf(var[c_glob] + BN_EPS) * gamma[c_glob];
        const float sh = beta[c_glob] - mean[c_glob] * sc;
#pragma unroll
        for (int nt = 0; nt < 16; nt++) {
            const int o = nt * 8 + tig * 2;
            float v0 = (acc[nt][2 * half]     + fcb[o])     * sc + sh;
            float v1 = (acc[nt][2 * half + 1] + fcb[o + 1]) * sc + sh;
            v0 = (v0 > 0.f) ? v0 : slope * v0;
            v1 = (v1 > 0.f) ? v1 : slope * v1;
            *(float2*)&y[r * W_ + o] = make_float2(v0, v1);
        }
    }
}

// ---------------------------------------------------------------------------
extern "C" void kernel_launch(void* const* d_in, const int* in_sizes, int n_in,
                              void* d_out, int out_size)
{
    const float* x     = (const float*)d_in[0];
    const float* wq    = (const float*)d_in[1];
    const float* bq    = (const float*)d_in[2];
    const float* wk    = (const float*)d_in[3];
    const float* bk    = (const float*)d_in[4];
    const float* wv    = (const float*)d_in[5];
    const float* bv    = (const float*)d_in[6];
    const float* fc_w  = (const float*)d_in[7];
    const float* fc_b  = (const float*)d_in[8];
    const float* gam   = (const float*)d_in[9];
    const float* bet   = (const float*)d_in[10];
    const float* mean  = (const float*)d_in[11];
    const float* var   = (const float*)d_in[12];
    const float* prelu = (const float*)d_in[13];
    float* y = (float*)d_out;

    cudaFuncSetAttribute(qkv_hmma, cudaFuncAttributeMaxDynamicSharedMemorySize, QKV_SMEM);
    cudaFuncSetAttribute(attn_fused_kernel, cudaFuncAttributeMaxDynamicSharedMemorySize, SMEM_ATTN);

    qkv_hmma<<<dim3(32, B_, 4), 256, QKV_SMEM>>>(x, wq, bq, wk, bk, wv, bv, fc_w);
    attn_fused_kernel<<<dim3(L_ / 128, NH, B_), 128, SMEM_ATTN>>>(
        fc_b, gam, bet, mean, var, prelu, y);
}

// round 16
// speedup vs baseline: 1.0153x; 1.0019x over previous
#include <cuda_runtime.h>
#include <cuda_fp16.h>
#include <cstdint>

// Problem constants
#define B_    4
#define CIN   128
#define COUT  128
#define H_    32
#define W_    128
#define L_    4096
#define NH    2
#define DK    64
#define BN_EPS 1e-5f

// q is pre-scaled by 0.125 * log2(e) so softmax is exp2(S)
#define QSCALE 0.18033688011112042f

// Device scratch (fp16 operands)
__device__ __half g_qhf[B_ * L_ * COUT];   // [b][l][c]  (pre-scaled)
__device__ __half g_khf[B_ * L_ * COUT];   // [b][l][c]
__device__ __half g_vhf[B_ * COUT * L_];   // [b][c][l]
__device__ __half g_fcwh[COUT * COUT];     // fcw hi  [o][w]
__device__ __half g_fcwl[COUT * COUT];     // fcw lo  [o][w]

#define SWZ128(off) ((off) ^ (((off) >> 3) & 0x70))
#define ONE2 0x3C003C00u   // fp16 {1.0, 1.0}

__device__ __forceinline__ uint32_t smem_u32(const void* p) {
    uint32_t a;
    asm("{ .reg .u64 t; cvta.to.shared.u64 t, %1; cvt.u32.u64 %0, t; }" : "=r"(a) : "l"(p));
    return a;
}
__device__ __forceinline__ void ldsm_x4(uint32_t* r, uint32_t addr) {
    asm volatile("ldmatrix.sync.aligned.m8n8.x4.shared.b16 {%0,%1,%2,%3}, [%4];"
                 : "=r"(r[0]), "=r"(r[1]), "=r"(r[2]), "=r"(r[3]) : "r"(addr));
}
__device__ __forceinline__ void mma_f16(float* d, const uint32_t* a, const uint32_t* b) {
    asm volatile(
        "mma.sync.aligned.m16n8k16.row.col.f32.f16.f16.f32 "
        "{%0,%1,%2,%3}, {%4,%5,%6,%7}, {%8,%9}, {%0,%1,%2,%3};"
        : "+f"(d[0]), "+f"(d[1]), "+f"(d[2]), "+f"(d[3])
        : "r"(a[0]), "r"(a[1]), "r"(a[2]), "r"(a[3]), "r"(b[0]), "r"(b[1]));
}
__device__ __forceinline__ void cp16(uint32_t dst, const void* src) {
    asm volatile("cp.async.ca.shared.global [%0], [%1], 16;" :: "r"(dst), "l"(src));
}
__device__ __forceinline__ uint32_t exp2_f16x2(float lo, float hi) {
    uint32_t s, p;
    asm("cvt.rn.f16x2.f32 %0, %1, %2;" : "=r"(s) : "f"(hi), "f"(lo));
    asm("ex2.approx.f16x2 %0, %1;" : "=r"(p) : "r"(s));
    return p;
}

// ---------------------------------------------------------------------------
// Kernel 1: QKV projection via HMMA (which 0..2) + fcw hi/lo split (which==3).
// ---------------------------------------------------------------------------
#define QKV_SMEM 65536
__global__ __launch_bounds__(256, 2)
void qkv_hmma(const float* __restrict__ x,
              const float* __restrict__ wq, const float* __restrict__ bq,
              const float* __restrict__ wk, const float* __restrict__ bk,
              const float* __restrict__ wv, const float* __restrict__ bv,
              const float* __restrict__ fcw)
{
    extern __shared__ char smc[];
    const uint32_t smb = smem_u32(smc);
    const int tid = threadIdx.x, wid = tid >> 5, lane = tid & 31;
    const int lt = blockIdx.x * 128, b = blockIdx.y, which = blockIdx.z;
    const int g = lane >> 2, tig = lane & 3;

    if (which == 3) {
        const int blk = blockIdx.y * 32 + blockIdx.x;
        if (blk < 16) {
            const int idx = blk * 256 + tid;   // 4096 float4s
            float4 v = ((const float4*)fcw)[idx];
            __half hi[4], lo[4];
            hi[0] = __float2half(v.x); lo[0] = __float2half(v.x - __half2float(hi[0]));
            hi[1] = __float2half(v.y); lo[1] = __float2half(v.y - __half2float(hi[1]));
            hi[2] = __float2half(v.z); lo[2] = __float2half(v.z - __half2float(hi[2]));
            hi[3] = __float2half(v.w); lo[3] = __float2half(v.w - __half2float(hi[3]));
            *(uint2*)&g_fcwh[idx * 4] = *(uint2*)hi;
            *(uint2*)&g_fcwl[idx * 4] = *(uint2*)lo;
        }
        return;
    }

    const float* w    = (which == 0) ? wq : (which == 1) ? wk : wv;
    const float* bias = (which == 0) ? bq : (which == 1) ? bk : bv;

    float4 xv[16];
#pragma unroll
    for (int u = 0; u < 16; u++) {
        int it = tid + u * 256;
        int l = it & 127, i4 = (it >> 7) * 4;
        const float* xp = &x[(size_t)(b * CIN + i4) * L_ + lt + l];
        xv[u].x = xp[0];
        xv[u].y = xp[L_];
        xv[u].z = xp[2 * L_];
        xv[u].w = xp[3 * L_];
    }
#pragma unroll
    for (int u = 0; u < 16; u++) {
        int it = tid + u * 256;
        int l = it & 127, i4 = (it >> 7) * 4;
        __half r[4] = {__float2half(xv[u].x), __float2half(xv[u].y),
                       __float2half(xv[u].z), __float2half(xv[u].w)};
        char* base = smc + ((i4 >> 6) ? 16384 : 0);
        *(uint2*)(base + SWZ128(l * 128 + (i4 & 63) * 2)) = *(uint2*)r;
    }
    float4 wv4[16];
#pragma unroll
    for (int u = 0; u < 16; u++) {
        int it = tid + u * 256;
        int o = it >> 5, i4 = (it & 31) * 4;
        wv4[u] = *(const float4*)&w[o * 128 + i4];
    }
#pragma unroll
    for (int u = 0; u < 16; u++) {
        int it = tid + u * 256;
        int o = it >> 5, i4 = (it & 31) * 4;
        __half r[4] = {__float2half(wv4[u].x), __float2half(wv4[u].y),
                       __float2half(wv4[u].z), __float2half(wv4[u].w)};
        char* base = smc + 32768 + ((i4 >> 6) ? 16384 : 0);
        *(uint2*)(base + SWZ128(o * 128 + (i4 & 63) * 2)) = *(uint2*)r;
    }
    __syncthreads();

    const uint32_t arow = wid * 16 + (lane & 7) + ((lane >> 3) & 1) * 8;
    const uint32_t acol = (lane >> 4) * 16;
    const uint32_t brow_lo  = (lane & 7) + ((lane >> 4) << 3);
    const uint32_t bcol_sel = ((lane >> 3) & 1) * 16;
    const int c0 = wid * 16 + g;

    float acc[16][4];
#pragma unroll
    for (int i = 0; i < 16; i++)
#pragma unroll
        for (int j = 0; j < 4; j++) acc[i][j] = 0.f;

#pragma unroll
    for (int kc = 0; kc < 8; kc++) {
        const uint32_t hoff = ((kc >> 2) ? 16384 : 0);
        const int ks = kc & 3;
        uint32_t a4[4];
        ldsm_x4(a4, smb + 32768 + hoff + SWZ128(arow * 128 + ks * 32 + acol));
#pragma unroll
        for (int np = 0; np < 8; np++) {
            uint32_t b4[4];
            ldsm_x4(b4, smb + hoff + SWZ128((np * 16 + brow_lo) * 128 + ks * 32 + bcol_sel));
            mma_f16(acc[2 * np],     a4, b4);
            mma_f16(acc[2 * np + 1], a4, b4 + 2);
        }
    }

    const float b0 = bias[c0], b1 = bias[c0 + 8];
    const float s = (which == 0) ? QSCALE : 1.0f;
    __syncthreads();

    if (which < 2) {
        __half* st = (__half*)smc;
#pragma unroll
        for (int nt = 0; nt < 16; nt++) {
            const int l0 = nt * 8 + tig * 2;
            st[l0 * 128 + c0]           = __float2half((acc[nt][0] + b0) * s);
            st[(l0 + 1) * 128 + c0]     = __float2half((acc[nt][1] + b0) * s);
            st[l0 * 128 + c0 + 8]       = __float2half((acc[nt][2] + b1) * s);
            st[(l0 + 1) * 128 + c0 + 8] = __float2half((acc[nt][3] + b1) * s);
        }
        __syncthreads();
        __half* dst = (which == 0) ? g_qhf : g_khf;
        uint4* dg = (uint4*)&dst[(size_t)(b * L_ + lt) * 128];
        const uint4* sg = (const uint4*)smc;
        for (int i = tid; i < 2048; i += 256) dg[i] = sg[i];
    } else {
        uint32_t* st = (uint32_t*)smc;
#pragma unroll
        for (int nt = 0; nt < 16; nt++) {
            const int lp = (nt * 8 + tig * 2) >> 1;
            __half2 v0 = __floats2half2_rn(acc[nt][0] + b0, acc[nt][1] + b0);
            __half2 v1 = __floats2half2_rn(acc[nt][2] + b1, acc[nt][3] + b1);
            st[c0 * 64 + lp]       = *(uint32_t*)&v0;
            st[(c0 + 8) * 64 + lp] = *(uint32_t*)&v1;
        }
        __syncthreads();
        for (int i = tid; i < 2048; i += 256) {
            int c = i >> 4, seg = i & 15;
            *(uint4*)&g_vhf[(size_t)(b * COUT + c) * L_ + lt + seg * 8] =
                ((const uint4*)smc)[i];
        }
    }
}

// ---------------------------------------------------------------------------
// Kernel 2: FMHA + FUSED fc/BN/PReLU. nb-loop SOFTWARE-PIPELINED:
// exp(S_cur) -> rowsum -> S_next MMAs (independent, fills MUFU shadow)
// -> PV(cur) -> rotate. Tensor pipe stays fed across the exp2 seam.
// ---------------------------------------------------------------------------
#define OFF_Q   0
#define OFF_S   16384
#define SMEM_ATTN 114688

__device__ __forceinline__ void load_kv_tile(uint32_t smb, int tid, int b, int head,
                                             int kt, int s)
{
    const char* kb = (const char*)g_khf;
    const uint32_t kdst = smb + OFF_S + s * 32768;
    for (int i = tid; i < 1024; i += 128) {
        int r = i >> 3, ch = i & 7;
        const char* src = kb + ((size_t)(b * L_ + kt + r) * COUT + head * DK) * 2 + ch * 16;
        cp16(kdst + SWZ128(r * 128 + ch * 16), src);
    }
    const char* vb = (const char*)g_vhf;
    const uint32_t vdst = kdst + 16384;
    for (int i = tid; i < 1024; i += 128) {
        int half = i >> 9, rem = i & 511;
        int d = rem >> 3, ch = rem & 7;
        const char* src = vb + ((size_t)(b * COUT + head * DK + d) * L_ + kt + half * 64 + ch * 8) * 2;
        cp16(vdst + half * 8192 + SWZ128(d * 128 + ch * 16), src);
    }
}

__global__ __launch_bounds__(128, 2)
void attn_fused_kernel(const float* __restrict__ fcb,
                       const float* __restrict__ gamma, const float* __restrict__ beta,
                       const float* __restrict__ mean,  const float* __restrict__ var,
                       const float* __restrict__ prelu, float* __restrict__ y)
{
    extern __shared__ char smc[];
    const uint32_t smb = smem_u32(smc);

    const int tid  = threadIdx.x;
    const int wid  = tid >> 5;
    const int lane = tid & 31;
    const int hidx = blockIdx.x;        // h row (qt = hidx*128)
    const int qt   = hidx * 128;
    const int head = blockIdx.y;
    const int b    = blockIdx.z;

    const int g   = lane >> 2;
    const int tig = lane & 3;

    // ---- prologue: Q + tiles 0 and 1 ----
    {
        const char* qb = (const char*)g_qhf;
        for (int i = tid; i < 1024; i += 128) {
            int r = i >> 3, ch = i & 7;
            const char* src = qb + ((size_t)(b * L_ + qt + r) * COUT + head * DK) * 2 + ch * 16;
            cp16(smb + OFF_Q + SWZ128(r * 128 + ch * 16), src);
        }
        load_kv_tile(smb, tid, b, head, 0, 0);
        asm volatile("cp.async.commit_group;" ::: "memory");
        load_kv_tile(smb, tid, b, head, 128, 1);
        asm volatile("cp.async.commit_group;" ::: "memory");
    }

    uint32_t qhr[2][4][4];
    float O[2][8][4];
    float Osum[2][4];
#pragma unroll
    for (int mi = 0; mi < 2; mi++) {
#pragma unroll
        for (int i = 0; i < 8; i++)
#pragma unroll
            for (int j = 0; j < 4; j++) O[mi][i][j] = 0.f;
#pragma unroll
        for (int j = 0; j < 4; j++) Osum[mi][j] = 0.f;
    }
    const uint32_t ones[2] = {ONE2, ONE2};

    const uint32_t brow_lo  = (lane & 7) + ((lane >> 4) << 3);
    const uint32_t bcol_sel = ((lane >> 3) & 1) * 16;

    int buf = 0;
    for (int t = 0; t < 32; t++) {
        if (t < 31) {
            asm volatile("cp.async.wait_group 1;" ::: "memory");
        } else {
            asm volatile("cp.async.wait_group 0;" ::: "memory");
        }
        __syncthreads();

        if (t == 0) {
#pragma unroll
            for (int mi = 0; mi < 2; mi++) {
                const uint32_t arow = wid * 32 + mi * 16 + (lane & 7) + ((lane >> 3) & 1) * 8;
#pragma unroll
                for (int ks = 0; ks < 4; ks++) {
                    uint32_t colb = ks * 32 + (lane >> 4) * 16;
                    ldsm_x4(qhr[mi][ks], smb + OFF_Q + SWZ128(arow * 128 + colb));
                }
            }
        }

        const uint32_t kbase = smb + OFF_S + buf * 32768;
        const uint32_t vbase = kbase + 16384;

        // ---- software-pipelined nb loop ----
        float Sa[2][2][4], Sb[2][2][4];

        // S(0) into Sa
#pragma unroll
        for (int mi = 0; mi < 2; mi++)
#pragma unroll
            for (int i = 0; i < 2; i++)
#pragma unroll
                for (int j = 0; j < 4; j++) Sa[mi][i][j] = 0.f;
        {
            const uint32_t krow = brow_lo;
#pragma unroll
            for (int ks = 0; ks < 4; ks++) {
                uint32_t bh[4];
                ldsm_x4(bh, kbase + SWZ128(krow * 128 + ks * 32 + bcol_sel));
                mma_f16(Sa[0][0], qhr[0][ks], bh);
                mma_f16(Sa[0][1], qhr[0][ks], bh + 2);
                mma_f16(Sa[1][0], qhr[1][ks], bh);
                mma_f16(Sa[1][1], qhr[1][ks], bh + 2);
            }
        }

#pragma unroll
        for (int nb = 0; nb < 8; nb++) {
            // exp of current block (consumes Sa)
            uint32_t pf[2][4];
#pragma unroll
            for (int mi = 0; mi < 2; mi++) {
                pf[mi][0] = exp2_f16x2(Sa[mi][0][0], Sa[mi][0][1]);
                pf[mi][1] = exp2_f16x2(Sa[mi][0][2], Sa[mi][0][3]);
                pf[mi][2] = exp2_f16x2(Sa[mi][1][0], Sa[mi][1][1]);
                pf[mi][3] = exp2_f16x2(Sa[mi][1][2], Sa[mi][1][3]);
            }

            // S(nb+1) into Sb — independent of pf; fills MUFU/cvt shadow
            if (nb < 7) {
#pragma unroll
                for (int mi = 0; mi < 2; mi++)
#pragma unroll
                    for (int i = 0; i < 2; i++)
#pragma unroll
                        for (int j = 0; j < 4; j++) Sb[mi][i][j] = 0.f;
                const uint32_t krow = (nb + 1) * 16 + brow_lo;
#pragma unroll
                for (int ks = 0; ks < 4; ks++) {
                    uint32_t bh[4];
                    ldsm_x4(bh, kbase + SWZ128(krow * 128 + ks * 32 + bcol_sel));
                    mma_f16(Sb[0][0], qhr[0][ks], bh);
                    mma_f16(Sb[0][1], qhr[0][ks], bh + 2);
                    mma_f16(Sb[1][0], qhr[1][ks], bh);
                    mma_f16(Sb[1][1], qhr[1][ks], bh + 2);
                }
            }

            // rowsum + PV of current block
            mma_f16(Osum[0], pf[0], ones);
            mma_f16(Osum[1], pf[1], ones);

            const uint32_t vb2 = vbase + ((nb >= 4) ? 8192 : 0);
#pragma unroll
            for (int dp = 0; dp < 4; dp++) {
                uint32_t vfr[4];
                uint32_t row = dp * 16 + brow_lo;
                ldsm_x4(vfr, vb2 + SWZ128(row * 128 + (nb & 3) * 32 + bcol_sel));
                mma_f16(O[0][2 * dp],     pf[0], vfr);
                mma_f16(O[0][2 * dp + 1], pf[0], vfr + 2);
                mma_f16(O[1][2 * dp],     pf[1], vfr);
                mma_f16(O[1][2 * dp + 1], pf[1], vfr + 2);
            }

            // rotate
#pragma unroll
            for (int mi = 0; mi < 2; mi++)
#pragma unroll
                for (int i = 0; i < 2; i++)
#pragma unroll
                    for (int j = 0; j < 4; j++) Sa[mi][i][j] = Sb[mi][i][j];
        }

        if (t + 2 < 32) {
            int nbuf = buf + 2; if (nbuf >= 3) nbuf -= 3;
            load_kv_tile(smb, tid, b, head, (t + 2) * 128, nbuf);
            asm volatile("cp.async.commit_group;" ::: "memory");
        }
        buf = (buf + 1 == 3) ? 0 : buf + 1;
    }

    // ================= FUSED fc EPILOGUE =================
    __syncthreads();   // all warps done with ring smem

    // ---- issue fcw hi/lo prefetch (F tiles @32768 hi, @65536 lo; 2x16K halves)
    {
        const char* fh = (const char*)g_fcwh;
        const char* fl = (const char*)g_fcwl;
        for (int i = tid; i < 2048; i += 128) {
            int o = i >> 4, seg = i & 15;
            int half = seg >> 3, c8 = seg & 7;
            uint32_t dst = half * 16384 + SWZ128(o * 128 + c8 * 16);
            size_t src = (size_t)o * 256 + half * 128 + c8 * 16;
            cp16(smb + 32768 + dst, fh + src);
            cp16(smb + 65536 + dst, fl + src);
        }
        asm volatile("cp.async.commit_group;" ::: "memory");
    }

    // ---- stage normalized O as hi/lo [c][w] tiles (A @0 hi, @16384 lo; halves +8192)
#pragma unroll
    for (int mi = 0; mi < 2; mi++) {
        const float inv0 = 1.f / Osum[mi][0];
        const float inv1 = 1.f / Osum[mi][2];
        const int q0 = wid * 32 + mi * 16 + g;
#pragma unroll
        for (int dt = 0; dt < 8; dt++) {
            const int c = dt * 8 + 2 * tig;
            float vals[4] = {O[mi][dt][0] * inv0, O[mi][dt][1] * inv0,
                             O[mi][dt][2] * inv1, O[mi][dt][3] * inv1};
            const int ws[4] = {q0, q0, q0 + 8, q0 + 8};
            const int cs[4] = {c, c + 1, c, c + 1};
#pragma unroll
            for (int j = 0; j < 4; j++) {
                __half hi = __float2half(vals[j]);
                __half lo = __float2half(vals[j] - __half2float(hi));
                const int w = ws[j];
                uint32_t off = ((w >> 6) ? 8192 : 0) + SWZ128(cs[j] * 128 + (w & 63) * 2);
                *(__half*)(smc + off)         = hi;
                *(__half*)(smc + 16384 + off) = lo;
            }
        }
    }
    asm volatile("cp.async.wait_group 0;" ::: "memory");
    __syncthreads();

    // ---- per-warp GEMM: 16 c-rows x 128 o, K = 128 w; per-np streaming frags
    const uint32_t arow = wid * 16 + (lane & 7) + ((lane >> 3) & 1) * 8;
    const uint32_t acol = (lane >> 4) * 16;

    float acc[16][4];
#pragma unroll
    for (int i = 0; i < 16; i++)
#pragma unroll
        for (int j = 0; j < 4; j++) acc[i][j] = 0.f;

#pragma unroll
    for (int kc = 0; kc < 8; kc++) {
        const int ks = kc & 3;
        const uint32_t ahalf = (kc >> 2) ? 8192 : 0;
        const uint32_t fhalf = (kc >> 2) ? 16384 : 0;
        uint32_t ah[4], al[4];
        const uint32_t aoff = ahalf + SWZ128(arow * 128 + ks * 32 + acol);
        ldsm_x4(ah, smb + aoff);
        ldsm_x4(al, smb + 16384 + aoff);

#pragma unroll
        for (int np = 0; np < 8; np++) {
            const uint32_t boff = fhalf + SWZ128((np * 16 + brow_lo) * 128 + ks * 32 + bcol_sel);
            uint32_t bh[4], bl[4];
            ldsm_x4(bh, smb + 32768 + boff);
            mma_f16(acc[2 * np],     ah, bh);
            mma_f16(acc[2 * np + 1], ah, bh + 2);
            ldsm_x4(bl, smb + 65536 + boff);
            mma_f16(acc[2 * np],     al, bh);
            mma_f16(acc[2 * np + 1], al, bh + 2);
            mma_f16(acc[2 * np],     ah, bl);
            mma_f16(acc[2 * np + 1], ah, bl + 2);
        }
    }

    // ---- bias + BN + PReLU -> y[b][c][h][o] ----
    const float slope = prelu[0];
#pragma unroll
    for (int half = 0; half < 2; half++) {
        const int cr = wid * 16 + g + 8 * half;     // c row within head (0..63)
        const int c_glob = head * DK + cr;          // BN channel
        const size_t r = ((size_t)(b * COUT + c_glob) * H_ + hidx);
        const float sc = rsqrtf(var[c_glob] + BN_EPS) * gamma[c_glob];
        const float sh = beta[c_glob] - mean[c_glob] * sc;
#pragma unroll
        for (int nt = 0; nt < 16; nt++) {
            const int o = nt * 8 + tig * 2;
            float v0 = (acc[nt][2 * half]     + fcb[o])     * sc + sh;
            float v1 = (acc[nt][2 * half + 1] + fcb[o + 1]) * sc + sh;
            v0 = (v0 > 0.f) ? v0 : slope * v0;
            v1 = (v1 > 0.f) ? v1 : slope * v1;
            *(float2*)&y[r * W_ + o] = make_float2(v0, v1);
        }
    }
}

// ---------------------------------------------------------------------------
extern "C" void kernel_launch(void* const* d_in, const int* in_sizes, int n_in,
                              void* d_out, int out_size)
{
    const float* x     = (const float*)d_in[0];
    const float* wq    = (const float*)d_in[1];
    const float* bq    = (const float*)d_in[2];
    const float* wk    = (const float*)d_in[3];
    const float* bk    = (const float*)d_in[4];
    const float* wv    = (const float*)d_in[5];
    const float* bv    = (const float*)d_in[6];
    const float* fc_w  = (const float*)d_in[7];
    const float* fc_b  = (const float*)d_in[8];
    const float* gam   = (const float*)d_in[9];
    const float* bet   = (const float*)d_in[10];
    const float* mean  = (const float*)d_in[11];
    const float* var   = (const float*)d_in[12];
    const float* prelu = (const float*)d_in[13];
    float* y = (float*)d_out;

    cudaFuncSetAttribute(qkv_hmma, cudaFuncAttributeMaxDynamicSharedMemorySize, QKV_SMEM);
    cudaFuncSetAttribute(attn_fused_kernel, cudaFuncAttributeMaxDynamicSharedMemorySize, SMEM_ATTN);

    qkv_hmma<<<dim3(32, B_, 4), 256, QKV_SMEM>>>(x, wq, bq, wk, bk, wv, bv, fc_w);
    attn_fused_kernel<<<dim3(L_ / 128, NH, B_), 128, SMEM_ATTN>>>(
        fc_b, gam, bet, mean, var, prelu, y);
}